// round 8
// baseline (speedup 1.0000x reference)
#include <cuda_runtime.h>
#include <cuda_bf16.h>

// ---------------------------------------------------------------------------
// mlp_forward_model_44495861187262
//
// restructured (segment_sum distributes over the linear layer):
//   aggH   = segment_sum(relu(x@W1a+b1a))            (pass 1: 5x64 per node)
//   agg    = aggH @ W1b + cnt*b1b                    (per graph)
//   G      = agg @ W2a[5:69] + b2a                   (per graph, b2a folded)
//   out    = relu(x@W2a[0:5] + G[batch]) @ W2b + b2b (pass 2)
//
// batch is int32 (JAX x64 disabled). edge_index is dead in the reference.
// All per-node math in packed f32x2 (FFMA2, rt_SMSP=2 like FFMA => 2x MACs).
// ---------------------------------------------------------------------------

#define N_GRAPHS 4096
#define HIDDEN   64
#define NODE_F   5
#define OUT_F    4

typedef unsigned long long ull;

// scratch (allocation-free rule: __device__ globals)
__device__ float g_aggH[N_GRAPHS * HIDDEN];
__device__ float g_cnt[N_GRAPHS];
__device__ float g_G[N_GRAPHS * HIDDEN];

// ---- f32x2 helpers ---------------------------------------------------------
__device__ __forceinline__ ull pk2(float lo, float hi) {
    ull r; asm("mov.b64 %0, {%1,%2};" : "=l"(r) : "f"(lo), "f"(hi)); return r;
}
__device__ __forceinline__ ull pkdup(float v) {
    ull r; asm("mov.b64 %0, {%1,%1};" : "=l"(r) : "f"(v)); return r;
}
__device__ __forceinline__ void upk2(ull v, float& lo, float& hi) {
    asm("mov.b64 {%0,%1}, %2;" : "=f"(lo), "=f"(hi) : "l"(v));
}
__device__ __forceinline__ void fma2(ull& d, ull a, ull b) {
    asm("fma.rn.f32x2 %0, %1, %2, %0;" : "+l"(d) : "l"(a), "l"(b));
}
__device__ __forceinline__ ull add2(ull a, ull b) {
    ull r; asm("add.rn.f32x2 %0, %1, %2;" : "=l"(r) : "l"(a), "l"(b)); return r;
}
__device__ __forceinline__ void relu2(ull& a) {
    float lo, hi; upk2(a, lo, hi);
    lo = fmaxf(lo, 0.0f); hi = fmaxf(hi, 0.0f);
    a = pk2(lo, hi);
}

// ---------------------------------------------------------------------------
__global__ void k_zero() {
    int i = blockIdx.x * blockDim.x + threadIdx.x;
    if (i < N_GRAPHS * HIDDEN) g_aggH[i] = 0.0f;
    if (i < N_GRAPHS)          g_cnt[i]  = 0.0f;
}

// ---------------------------------------------------------------------------
// Pass 1: warp owns 64 contiguous nodes. Lane owns channels c0=lane, c1=lane+32.
// Nodes processed in PAIRS packed into f32x2 lanes: xp[k]=(x_n[k], x_{n+1}[k]);
// accumulators stay packed (halves summed only at flush). batch sorted =>
// graph id warp-uniform; atomic flush only at segment boundaries.
#define NPW 64

__global__ void k_pass1(const float* __restrict__ x,
                        const int* __restrict__ batch,
                        const float* __restrict__ W1a,
                        const float* __restrict__ b1a,
                        int N) {
    int warp = (blockIdx.x * blockDim.x + threadIdx.x) >> 5;
    int lane = threadIdx.x & 31;
    long long start = (long long)warp * NPW;
    if (start >= N) return;

    const int c0 = lane, c1 = lane + 32;

    float w0s[NODE_F], w1s[NODE_F];
    ull   w0d[NODE_F], w1d[NODE_F];
#pragma unroll
    for (int k = 0; k < NODE_F; k++) {
        w0s[k] = __ldg(W1a + k * HIDDEN + c0);
        w1s[k] = __ldg(W1a + k * HIDDEN + c1);
        w0d[k] = pkdup(w0s[k]);
        w1d[k] = pkdup(w1s[k]);
    }
    const float b0s = __ldg(b1a + c0);
    const float b1s = __ldg(b1a + c1);
    const ull   b0d = pkdup(b0s);
    const ull   b1d = pkdup(b1s);

    unsigned cur_g;
    {
        unsigned g = (unsigned)__ldg(batch + start);
        cur_g = (g < N_GRAPHS) ? g : 0u;
    }
    ull acc0 = 0, acc1 = 0;
    float cnt = 0.0f;

#define P1_FLUSH() do {                                            \
        float lo, hi;                                              \
        upk2(acc0, lo, hi);                                        \
        atomicAdd(&g_aggH[cur_g * HIDDEN + c0], lo + hi);          \
        upk2(acc1, lo, hi);                                        \
        atomicAdd(&g_aggH[cur_g * HIDDEN + c1], lo + hi);          \
        if (lane == 0) atomicAdd(&g_cnt[cur_g], cnt);              \
        acc0 = 0; acc1 = 0; cnt = 0.0f;                            \
    } while (0)

    // packed pair: nodes at xr[i0*5+k], xr[(i0+1)*5+k]
#define P1_PAIR(i0) do {                                           \
        ull h0 = b0d, h1 = b1d;                                    \
        _Pragma("unroll")                                          \
        for (int k = 0; k < NODE_F; k++) {                         \
            ull xp = pk2(xr[(i0) * NODE_F + k],                    \
                         xr[(i0 + 1) * NODE_F + k]);               \
            fma2(h0, xp, w0d[k]);                                  \
            fma2(h1, xp, w1d[k]);                                  \
        }                                                          \
        relu2(h0); relu2(h1);                                      \
        acc0 = add2(acc0, h0);                                     \
        acc1 = add2(acc1, h1);                                     \
    } while (0)

    // scalar single node (slow path at segment boundaries)
#define P1_ONE(i) do {                                             \
        float h0 = b0s, h1 = b1s;                                  \
        _Pragma("unroll")                                          \
        for (int k = 0; k < NODE_F; k++) {                         \
            h0 = fmaf(xr[(i) * NODE_F + k], w0s[k], h0);           \
            h1 = fmaf(xr[(i) * NODE_F + k], w1s[k], h1);           \
        }                                                          \
        acc0 = add2(acc0, pk2(fmaxf(h0, 0.0f), 0.0f));             \
        acc1 = add2(acc1, pk2(fmaxf(h1, 0.0f), 0.0f));             \
        cnt += 1.0f;                                               \
    } while (0)

    if (start + NPW <= N) {
        const float4* xv  = (const float4*)(x + start * NODE_F);
        const int4*   bvv = (const int4*)(batch + start);
#pragma unroll 2
        for (int grp = 0; grp < NPW / 4; grp++) {
            int4 bg = __ldg(bvv + grp);
            float4 v0 = __ldg(xv + grp * 5 + 0);
            float4 v1 = __ldg(xv + grp * 5 + 1);
            float4 v2 = __ldg(xv + grp * 5 + 2);
            float4 v3 = __ldg(xv + grp * 5 + 3);
            float4 v4 = __ldg(xv + grp * 5 + 4);
            float xr[20] = { v0.x, v0.y, v0.z, v0.w,
                             v1.x, v1.y, v1.z, v1.w,
                             v2.x, v2.y, v2.z, v2.w,
                             v3.x, v3.y, v3.z, v3.w,
                             v4.x, v4.y, v4.z, v4.w };
            if ((unsigned)bg.w == cur_g) {     // sorted => all 4 in cur_g
                P1_PAIR(0);
                P1_PAIR(2);
                cnt += 4.0f;
            } else {
                int gs[4] = { bg.x, bg.y, bg.z, bg.w };
#pragma unroll
                for (int i = 0; i < 4; i++) {
                    unsigned g = (unsigned)gs[i];
                    if (g >= N_GRAPHS) g = 0;
                    if (g != cur_g) { P1_FLUSH(); cur_g = g; }
                    P1_ONE(i);
                }
            }
        }
    } else {
        long long end = N;
        for (long long n = start; n < end; n++) {
            unsigned g = (unsigned)__ldg(batch + n);
            if (g >= N_GRAPHS) g = 0;
            if (g != cur_g) { P1_FLUSH(); cur_g = g; }
            float xr[NODE_F];
#pragma unroll
            for (int k = 0; k < NODE_F; k++) xr[k] = __ldg(x + n * NODE_F + k);
            P1_ONE(0);
        }
    }
    P1_FLUSH();
#undef P1_ONE
#undef P1_PAIR
#undef P1_FLUSH
}

// ---------------------------------------------------------------------------
// Per-graph: t = aggH@W1b + cnt*b1b ; G = t @ W2a[5:69] + b2a (b2a folded)
__global__ void k_graph(const float* __restrict__ W1b,
                        const float* __restrict__ b1b,
                        const float* __restrict__ W2a,
                        const float* __restrict__ b2a) {
    int g = blockIdx.x;
    int c = threadIdx.x;          // 64 threads
    __shared__ float sah[HIDDEN];
    __shared__ float t[HIDDEN];
    __shared__ float scnt;

    sah[c] = g_aggH[g * HIDDEN + c];
    if (c == 0) scnt = g_cnt[g];
    __syncthreads();

    float acc = scnt * __ldg(b1b + c);
#pragma unroll 8
    for (int k = 0; k < HIDDEN; k++)
        acc = fmaf(sah[k], __ldg(W1b + k * HIDDEN + c), acc);
    t[c] = acc;
    __syncthreads();

    float gacc = __ldg(b2a + c);
#pragma unroll 8
    for (int k = 0; k < HIDDEN; k++)
        gacc = fmaf(t[k], __ldg(W2a + (NODE_F + k) * HIDDEN + c), gacc);
    g_G[g * HIDDEN + c] = gacc;
}

// ---------------------------------------------------------------------------
// Pass 2: 4 nodes per thread, 1024 nodes per 256-thread block.
// Weight record per channel pair p (channels 2p,2p+1), 20 floats, 16B-aligned:
//   [0:8)  w_k pairs k=0..3   [8:16) wb_j pairs j=0..3   [16:18) w_4 pair
// G rows (b2a folded) for the block's graph span staged in smem; span is
// block-uniform so the fast/slow choice is divergence-free.
#define P2_NODES 1024
#define P2_SGMAX 24

__global__ void __launch_bounds__(256, 2)
k_pass2(const float* __restrict__ x,
        const int* __restrict__ batch,
        const float* __restrict__ W2a,
        const float* __restrict__ W2b,
        const float* __restrict__ b2b,
        float* __restrict__ out,
        int N) {
    __shared__ __align__(16) float sw[(HIDDEN / 2) * 20];
    __shared__ __align__(16) float sx[P2_NODES * NODE_F];
    __shared__ __align__(16) float sG[P2_SGMAX * HIDDEN];

    const int tid = threadIdx.x;
    const long long base = (long long)blockIdx.x * P2_NODES;
    int nmax = (int)(N - base); if (nmax > P2_NODES) nmax = P2_NODES;

    // stage weight records
    for (int i = tid; i < (HIDDEN / 2) * 20; i += 256) {
        int p = i / 20, f = i % 20;
        float v = 0.0f;
        int ch = 2 * p + (f & 1);
        if (f < 8)       v = W2a[(f >> 1) * HIDDEN + ch];
        else if (f < 16) v = W2b[ch * OUT_F + ((f - 8) >> 1)];
        else if (f < 18) v = W2a[4 * HIDDEN + ch];
        sw[i] = v;
    }

    // stage x (float4 main + scalar tail)
    {
        int nf  = nmax * NODE_F;
        int nf4 = nf >> 2;
        const float4* xs4 = (const float4*)(x + base * NODE_F);
        float4* sx4 = (float4*)sx;
        for (int i = tid; i < nf4; i += 256) sx4[i] = __ldg(xs4 + i);
        for (int i = nf4 * 4 + tid; i < nf; i += 256) sx[i] = __ldg(x + base * NODE_F + i);
    }

    // graph span (block-uniform) + stage G rows
    unsigned g0;
    int span;
    {
        unsigned ga = (unsigned)__ldg(batch + base);
        unsigned gb = (unsigned)__ldg(batch + base + nmax - 1);
        if (ga >= N_GRAPHS) ga = 0;
        if (gb >= N_GRAPHS) gb = 0;
        g0 = ga;
        span = (int)gb - (int)ga + 1;
        if (span < 1) span = 1;
    }
    int rows = span > P2_SGMAX ? P2_SGMAX : span;
    for (int i = tid; i < rows * (HIDDEN / 4); i += 256) {
        ((float4*)sG)[i] = __ldg((const float4*)(g_G + (long long)g0 * HIDDEN) + i);
    }
    __syncthreads();

    // per-thread nodes
    long long nI[4];
    bool vI[4];
    unsigned gI[4];
#pragma unroll
    for (int q = 0; q < 4; q++) {
        nI[q] = base + tid + 256 * q;
        vI[q] = nI[q] < N;
        unsigned g = (unsigned)__ldg(batch + (vI[q] ? nI[q] : base));
        if (g >= N_GRAPHS) g = 0;
        gI[q] = g;
    }

    // pack x (invalid nodes alias node 0's data)
    ull xpA[NODE_F], xpB[NODE_F], xpC[NODE_F], xpD[NODE_F];
    {
        const float* xa = sx + tid * NODE_F;
        const float* xb = vI[1] ? sx + (tid + 256) * NODE_F : xa;
        const float* xc = vI[2] ? sx + (tid + 512) * NODE_F : xa;
        const float* xd = vI[3] ? sx + (tid + 768) * NODE_F : xa;
#pragma unroll
        for (int k = 0; k < NODE_F; k++) {
            xpA[k] = pkdup(xa[k]);
            xpB[k] = pkdup(xb[k]);
            xpC[k] = pkdup(xc[k]);
            xpD[k] = pkdup(xd[k]);
        }
    }

    ull a0 = 0, a1 = 0, a2 = 0, a3 = 0;
    ull b0 = 0, b1 = 0, b2 = 0, b3 = 0;
    ull c0 = 0, c1 = 0, c2 = 0, c3 = 0;
    ull d0 = 0, d1 = 0, d2 = 0, d3 = 0;

#define P2_LOOP(LOADG_A, LOADG_B, LOADG_C, LOADG_D)                         \
    _Pragma("unroll 8")                                                     \
    for (int p = 0; p < HIDDEN / 2; p++) {                                  \
        const float* rec = sw + p * 20;                                     \
        ulonglong2 q0 = *reinterpret_cast<const ulonglong2*>(rec);          \
        ulonglong2 q1 = *reinterpret_cast<const ulonglong2*>(rec + 4);      \
        ulonglong2 q2 = *reinterpret_cast<const ulonglong2*>(rec + 8);      \
        ulonglong2 q3 = *reinterpret_cast<const ulonglong2*>(rec + 12);     \
        ull w4 = *reinterpret_cast<const ull*>(rec + 16);                   \
        ull hA = (LOADG_A); ull hB = (LOADG_B);                             \
        ull hC = (LOADG_C); ull hD = (LOADG_D);                             \
        fma2(hA, xpA[0], q0.x); fma2(hB, xpB[0], q0.x);                     \
        fma2(hC, xpC[0], q0.x); fma2(hD, xpD[0], q0.x);                     \
        fma2(hA, xpA[1], q0.y); fma2(hB, xpB[1], q0.y);                     \
        fma2(hC, xpC[1], q0.y); fma2(hD, xpD[1], q0.y);                     \
        fma2(hA, xpA[2], q1.x); fma2(hB, xpB[2], q1.x);                     \
        fma2(hC, xpC[2], q1.x); fma2(hD, xpD[2], q1.x);                     \
        fma2(hA, xpA[3], q1.y); fma2(hB, xpB[3], q1.y);                     \
        fma2(hC, xpC[3], q1.y); fma2(hD, xpD[3], q1.y);                     \
        fma2(hA, xpA[4], w4);   fma2(hB, xpB[4], w4);                       \
        fma2(hC, xpC[4], w4);   fma2(hD, xpD[4], w4);                       \
        relu2(hA); relu2(hB); relu2(hC); relu2(hD);                         \
        fma2(a0, hA, q2.x); fma2(b0, hB, q2.x);                             \
        fma2(c0, hC, q2.x); fma2(d0, hD, q2.x);                             \
        fma2(a1, hA, q2.y); fma2(b1, hB, q2.y);                             \
        fma2(c1, hC, q2.y); fma2(d1, hD, q2.y);                             \
        fma2(a2, hA, q3.x); fma2(b2, hB, q3.x);                             \
        fma2(c2, hC, q3.x); fma2(d2, hD, q3.x);                             \
        fma2(a3, hA, q3.y); fma2(b3, hB, q3.y);                             \
        fma2(c3, hC, q3.y); fma2(d3, hD, q3.y);                             \
    }

    if (span <= P2_SGMAX) {
        // all G rows staged in smem (LDS broadcast-friendly)
        const int oA = (int)(gI[0] - g0) * HIDDEN;
        const int oB = (int)(gI[1] - g0) * HIDDEN;
        const int oC = (int)(gI[2] - g0) * HIDDEN;
        const int oD = (int)(gI[3] - g0) * HIDDEN;
        P2_LOOP(*reinterpret_cast<const ull*>(sG + oA + 2 * p),
                *reinterpret_cast<const ull*>(sG + oB + 2 * p),
                *reinterpret_cast<const ull*>(sG + oC + 2 * p),
                *reinterpret_cast<const ull*>(sG + oD + 2 * p))
    } else {
        // rare fallback: G straight from global
        const float* GA = g_G + (long long)gI[0] * HIDDEN;
        const float* GB = g_G + (long long)gI[1] * HIDDEN;
        const float* GC = g_G + (long long)gI[2] * HIDDEN;
        const float* GD = g_G + (long long)gI[3] * HIDDEN;
        P2_LOOP(*reinterpret_cast<const ull*>(GA + 2 * p),
                *reinterpret_cast<const ull*>(GB + 2 * p),
                *reinterpret_cast<const ull*>(GC + 2 * p),
                *reinterpret_cast<const ull*>(GD + 2 * p))
    }
#undef P2_LOOP

    float4 bb = __ldg((const float4*)b2b);
    float lo, hi;
    float4 o;

    upk2(a0, lo, hi); o.x = lo + hi + bb.x;
    upk2(a1, lo, hi); o.y = lo + hi + bb.y;
    upk2(a2, lo, hi); o.z = lo + hi + bb.z;
    upk2(a3, lo, hi); o.w = lo + hi + bb.w;
    ((float4*)out)[nI[0]] = o;

    if (vI[1]) {
        upk2(b0, lo, hi); o.x = lo + hi + bb.x;
        upk2(b1, lo, hi); o.y = lo + hi + bb.y;
        upk2(b2, lo, hi); o.z = lo + hi + bb.z;
        upk2(b3, lo, hi); o.w = lo + hi + bb.w;
        ((float4*)out)[nI[1]] = o;
    }
    if (vI[2]) {
        upk2(c0, lo, hi); o.x = lo + hi + bb.x;
        upk2(c1, lo, hi); o.y = lo + hi + bb.y;
        upk2(c2, lo, hi); o.z = lo + hi + bb.z;
        upk2(c3, lo, hi); o.w = lo + hi + bb.w;
        ((float4*)out)[nI[2]] = o;
    }
    if (vI[3]) {
        upk2(d0, lo, hi); o.x = lo + hi + bb.x;
        upk2(d1, lo, hi); o.y = lo + hi + bb.y;
        upk2(d2, lo, hi); o.z = lo + hi + bb.z;
        upk2(d3, lo, hi); o.w = lo + hi + bb.w;
        ((float4*)out)[nI[3]] = o;
    }
}

// ---------------------------------------------------------------------------
extern "C" void kernel_launch(void* const* d_in, const int* in_sizes, int n_in,
                              void* d_out, int out_size) {
    const float* x     = (const float*)d_in[0];
    const int*   batch = (const int*)d_in[2];     // int32 (JAX x64 disabled)
    int wb = n_in - 8;
    const float* W1a = (const float*)d_in[wb + 0];
    const float* b1a = (const float*)d_in[wb + 1];
    const float* W1b = (const float*)d_in[wb + 2];
    const float* b1b = (const float*)d_in[wb + 3];
    const float* W2a = (const float*)d_in[wb + 4];
    const float* b2a = (const float*)d_in[wb + 5];
    const float* W2b = (const float*)d_in[wb + 6];
    const float* b2b = (const float*)d_in[wb + 7];
    float* out = (float*)d_out;

    int N = in_sizes[0] / NODE_F;

    // K0: zero scratch
    k_zero<<<(N_GRAPHS * HIDDEN + 255) / 256, 256>>>();

    // K1: pass 1 (segment-summed hidden h)
    {
        long long warps = ((long long)N + NPW - 1) / NPW;
        int blocks = (int)((warps * 32 + 255) / 256);
        k_pass1<<<blocks, 256>>>(x, batch, W1a, b1a, N);
    }

    // K2: per-graph GEMMs (b2a folded into G)
    k_graph<<<N_GRAPHS, HIDDEN>>>(W1b, b1b, W2a, b2a);

    // K3: pass 2 (output)
    {
        int blocks = (int)(((long long)N + P2_NODES - 1) / P2_NODES);
        k_pass2<<<blocks, 256>>>(x, batch, W2a, W2b, b2b, out, N);
    }
}